// round 2
// baseline (speedup 1.0000x reference)
#include <cuda_runtime.h>
#include <cstddef>

#define BB   4
#define CC   16
#define HH   256
#define WW   256
#define KK   9
#define EPSF 1e-20f

// One thread = 2 horizontally adjacent pixels (float2).
// gid in [0, B*H*W/2): w0 = 2*(gid & 127) ; h = (gid>>7)&255 ; b = gid>>15.
__global__ __launch_bounds__(256, 2)
void struct_nconv_fused_kernel(const float* __restrict__ d,
                               const float* __restrict__ cd,
                               const float* __restrict__ spr,
                               const float* __restrict__ swg,
                               const float* __restrict__ cwg,
                               float* __restrict__ out)
{
    __shared__ float s_sw[144];   // spatial_weight[c*9+k]
    __shared__ float s_cw[256];   // channel_weight[o*16+c]
    __shared__ float s_sums[2];   // {sum(sw), sum(cw)}

    const int tid = threadIdx.x;
    if (tid < 144) s_sw[tid] = swg[tid];
    s_cw[tid] = cwg[tid];
    __syncthreads();

    const int warp = tid >> 5, lane = tid & 31;
    if (warp == 0) {
        float v = 0.f;
        #pragma unroll
        for (int j = 0; j < 5; ++j) {
            int idx = lane + 32 * j;
            if (idx < 144) v += s_sw[idx];
        }
        #pragma unroll
        for (int off = 16; off; off >>= 1) v += __shfl_down_sync(0xffffffffu, v, off);
        if (lane == 0) s_sums[0] = v;
    } else if (warp == 1) {
        float v = 0.f;
        #pragma unroll
        for (int j = 0; j < 8; ++j) v += s_cw[lane + 32 * j];
        #pragma unroll
        for (int off = 16; off; off >>= 1) v += __shfl_down_sync(0xffffffffu, v, off);
        if (lane == 0) s_sums[1] = v;
    }
    __syncthreads();

    const float f_sw   = 1.0f / (s_sums[0] + EPSF);  // 1/(sum spatial_weight + eps)
    const float inv_cw = f_sw / (s_sums[1] + EPSF);  // folds cd_out = D*f_sw / (sum cw + eps)

    const int gid = blockIdx.x * 256 + tid;          // 0 .. 131071
    const int w0  = (gid & 127) << 1;
    const int rem = gid >> 7;
    const int h   = rem & 255;
    const int b   = rem >> 8;

    const bool wl = (w0 > 0);
    const bool wr = (w0 + 2 < WW);

    const size_t planeHW = (size_t)HH * WW;
    const float* dB  = d   + (size_t)b * CC * planeHW;
    const float* cdB = cd  + (size_t)b * CC * planeHW;
    const float* spB = spr + (size_t)b * CC * KK * planeHW + (size_t)h * WW + w0;

    float2 accN[16], accD[16];
    #pragma unroll
    for (int o = 0; o < 16; ++o) {
        accN[o] = make_float2(0.f, 0.f);
        accD[o] = make_float2(0.f, 0.f);
    }

    #pragma unroll 1
    for (int c = 0; c < CC; ++c) {
        const float* dC  = dB  + (size_t)c * planeHW;
        const float* cdC = cdB + (size_t)c * planeHW;
        const float* spC = spB + (size_t)c * KK * planeHW;

        // hoist this channel's 9 spatial weights into registers
        float swr[9];
        #pragma unroll
        for (int k = 0; k < 9; ++k) swr[k] = s_sw[c * 9 + k];

        float nomx = 0.f, nomy = 0.f, denx = 0.f, deny = 0.f;

        #pragma unroll
        for (int i = 0; i < 3; ++i) {
            const int hh = h + i - 1;
            const bool rok = (hh >= 0) && (hh < HH);
            const float* dR  = dC  + (size_t)hh * WW + w0;
            const float* cdR = cdC + (size_t)hh * WW + w0;

            float  dm  = (rok && wl) ? dR[-1]  : 0.f;
            float2 dc  = rok ? *(const float2*)dR  : make_float2(0.f, 0.f);
            float  dp  = (rok && wr) ? dR[2]   : 0.f;
            float  cm  = (rok && wl) ? cdR[-1] : 0.f;
            float2 ccv = rok ? *(const float2*)cdR : make_float2(0.f, 0.f);
            float  cp  = (rok && wr) ? cdR[2]  : 0.f;

            const float dw[4]  = { dm, dc.x,  dc.y,  dp };
            const float cdw[4] = { cm, ccv.x, ccv.y, cp };

            #pragma unroll
            for (int j = 0; j < 3; ++j) {
                const int k = i * 3 + j;
                const float2 sp = *(const float2*)(spC + (size_t)k * planeHW);
                const float swv = swr[k];
                const float tx = cdw[j]     * sp.x;
                const float ty = cdw[j + 1] * sp.y;
                denx = fmaf(tx, swv, denx);
                deny = fmaf(ty, swv, deny);
                nomx = fmaf(tx * dw[j],     swv, nomx);
                nomy = fmaf(ty * dw[j + 1], swv, nomy);
            }
        }

        // channel-mix rank-1 update
        #pragma unroll
        for (int o = 0; o < 16; ++o) {
            const float cwv = s_cw[o * 16 + c];
            accN[o].x = fmaf(nomx, cwv, accN[o].x);
            accN[o].y = fmaf(nomy, cwv, accN[o].y);
            accD[o].x = fmaf(denx, cwv, accD[o].x);
            accD[o].y = fmaf(deny, cwv, accD[o].y);
        }
    }

    const size_t Ntot    = (size_t)BB * CC * planeHW;
    const size_t pixbase = (size_t)b * CC * planeHW + (size_t)h * WW + w0;

    #pragma unroll
    for (int o = 0; o < 16; ++o) {
        // d_out = (N*f_sw)/(D*f_sw+EPS) == N/(D + EPS/f_sw) ~= N/(D+EPS)
        float2 dov, cdo;
        dov.x = accN[o].x / (accD[o].x + EPSF);
        dov.y = accN[o].y / (accD[o].y + EPSF);
        cdo.x = accD[o].x * inv_cw;   // devalue_conf = 1 (stride 1)
        cdo.y = accD[o].y * inv_cw;
        const size_t idx = pixbase + (size_t)o * planeHW;
        *(float2*)(out + idx)        = dov;
        *(float2*)(out + Ntot + idx) = cdo;
    }
}

extern "C" void kernel_launch(void* const* d_in, const int* in_sizes, int n_in,
                              void* d_out, int out_size)
{
    const float* d   = (const float*)d_in[0];
    const float* cd  = (const float*)d_in[1];
    // d_in[2] = s, d_in[3] = cs : unused by the reference computation
    const float* spr = (const float*)d_in[4];
    const float* sw  = (const float*)d_in[5];
    const float* cw  = (const float*)d_in[6];
    float* out = (float*)d_out;

    // B*H*W/2 threads = 131072 -> 512 blocks of 256
    struct_nconv_fused_kernel<<<512, 256>>>(d, cd, spr, sw, cw, out);
}

// round 3
// speedup vs baseline: 1.2851x; 1.2851x over previous
#include <cuda_runtime.h>
#include <cstddef>

#define BB   4
#define CC   16
#define HH   256
#define WW   256
#define EPSF 1e-20f

// Two-stage split kernel.
// Block = 256 threads = 16 pixel-pairs x 16 channels.
// Stage 1: thread (p, c) computes spatial nom/den for one channel of one
//          pixel-pair (2 adjacent pixels, float2 loads), writes to smem.
// Stage 2: thread (p, o) does the 16-wide channel mix from smem and stores.
__global__ __launch_bounds__(256, 4)
void struct_nconv_split_kernel(const float* __restrict__ d,
                               const float* __restrict__ cd,
                               const float* __restrict__ spr,
                               const float* __restrict__ swg,
                               const float* __restrict__ cwg,
                               float* __restrict__ out)
{
    __shared__ float  s_sw[144];      // spatial_weight[c*9+k]
    __shared__ float  s_cw[256];      // channel_weight[o*16+c]
    __shared__ float  s_sums[2];      // {sum(sw), sum(cw)}
    __shared__ float4 s_nd[16][16];   // [c][p] = (nomx, nomy, denx, deny)

    const int tid = threadIdx.x;
    if (tid < 144) s_sw[tid] = swg[tid];
    s_cw[tid] = cwg[tid];
    __syncthreads();

    // weight sums (warps 0/1); consumed only after the next __syncthreads
    const int warp = tid >> 5, lane = tid & 31;
    if (warp == 0) {
        float v = 0.f;
        #pragma unroll
        for (int j = 0; j < 5; ++j) {
            int idx = lane + 32 * j;
            if (idx < 144) v += s_sw[idx];
        }
        #pragma unroll
        for (int off = 16; off; off >>= 1) v += __shfl_down_sync(0xffffffffu, v, off);
        if (lane == 0) s_sums[0] = v;
    } else if (warp == 1) {
        float v = 0.f;
        #pragma unroll
        for (int j = 0; j < 8; ++j) v += s_cw[lane + 32 * j];
        #pragma unroll
        for (int off = 16; off; off >>= 1) v += __shfl_down_sync(0xffffffffu, v, off);
        if (lane == 0) s_sums[1] = v;
    }

    // ---------------- Stage 1: spatial nom/den, one channel per thread ----
    const int p  = tid & 15;               // pixel-pair within block
    const int c  = tid >> 4;               // channel
    const int pp = blockIdx.x * 16 + p;    // global pixel-pair 0..131071
    const int w0 = (pp & 127) << 1;
    const int h  = (pp >> 7) & 255;
    const int b  = pp >> 15;

    const bool wl = (w0 > 0);
    const bool wr = (w0 + 2 < WW);

    const size_t HW = (size_t)HH * WW;
    const float* dC  = d   + ((size_t)b * CC + c) * HW;
    const float* cdC = cd  + ((size_t)b * CC + c) * HW;
    const float* spC = spr + ((size_t)b * CC + c) * 9 * HW + (size_t)h * WW + w0;

    float swr[9];
    #pragma unroll
    for (int k = 0; k < 9; ++k) swr[k] = s_sw[c * 9 + k];

    float nomx = 0.f, nomy = 0.f, denx = 0.f, deny = 0.f;

    #pragma unroll
    for (int i = 0; i < 3; ++i) {
        const int hh = h + i - 1;
        const bool rok = (hh >= 0) && (hh < HH);
        const float* dR  = dC  + (size_t)hh * WW + w0;
        const float* cdR = cdC + (size_t)hh * WW + w0;

        float  dm  = (rok && wl) ? dR[-1]  : 0.f;
        float2 dc  = rok ? *(const float2*)dR  : make_float2(0.f, 0.f);
        float  dp  = (rok && wr) ? dR[2]   : 0.f;
        float  cm  = (rok && wl) ? cdR[-1] : 0.f;
        float2 ccv = rok ? *(const float2*)cdR : make_float2(0.f, 0.f);
        float  cp  = (rok && wr) ? cdR[2]  : 0.f;

        const float dw[4]  = { dm, dc.x,  dc.y,  dp };
        const float cdw[4] = { cm, ccv.x, ccv.y, cp };

        #pragma unroll
        for (int j = 0; j < 3; ++j) {
            const int k = i * 3 + j;
            const float2 sp  = *(const float2*)(spC + (size_t)k * HW);
            const float  swv = swr[k];
            const float tx = cdw[j]     * sp.x;
            const float ty = cdw[j + 1] * sp.y;
            denx = fmaf(tx, swv, denx);
            deny = fmaf(ty, swv, deny);
            nomx = fmaf(tx * dw[j],     swv, nomx);
            nomy = fmaf(ty * dw[j + 1], swv, nomy);
        }
    }

    s_nd[c][p] = make_float4(nomx, nomy, denx, deny);
    __syncthreads();

    // ---------------- Stage 2: channel mix, one output channel per thread --
    const int o = c;  // tid>>4 reinterpreted as output channel; same (p,b,h,w0)

    float2 aN = make_float2(0.f, 0.f);
    float2 aD = make_float2(0.f, 0.f);
    #pragma unroll
    for (int cc = 0; cc < 16; ++cc) {
        const float4 nd  = s_nd[cc][p];
        const float  cwv = s_cw[o * 16 + cc];
        aN.x = fmaf(nd.x, cwv, aN.x);
        aN.y = fmaf(nd.y, cwv, aN.y);
        aD.x = fmaf(nd.z, cwv, aD.x);
        aD.y = fmaf(nd.w, cwv, aD.y);
    }

    // d_out = N/(D+EPS) (EPS-cancellation, error O(1e-19));
    // cd_out = (D / (sum sw + eps)) / (sum cw + eps)   (devalue_conf = 1)
    const float inv_cw = 1.0f / ((s_sums[0] + EPSF) * (s_sums[1] + EPSF));

    float2 dov, cdo;
    dov.x = aN.x / (aD.x + EPSF);
    dov.y = aN.y / (aD.y + EPSF);
    cdo.x = aD.x * inv_cw;
    cdo.y = aD.y * inv_cw;

    const size_t Ntot = (size_t)BB * CC * HW;
    const size_t idx  = ((size_t)b * CC + o) * HW + (size_t)h * WW + w0;
    *(float2*)(out + idx)        = dov;
    *(float2*)(out + Ntot + idx) = cdo;
}

extern "C" void kernel_launch(void* const* d_in, const int* in_sizes, int n_in,
                              void* d_out, int out_size)
{
    const float* d   = (const float*)d_in[0];
    const float* cd  = (const float*)d_in[1];
    // d_in[2] = s, d_in[3] = cs : unused by the reference computation
    const float* spr = (const float*)d_in[4];
    const float* sw  = (const float*)d_in[5];
    const float* cw  = (const float*)d_in[6];
    float* out = (float*)d_out;

    // 131072 pixel-pairs / 16 per block = 8192 blocks
    struct_nconv_split_kernel<<<8192, 256>>>(d, cd, spr, sw, cw, out);
}

// round 4
// speedup vs baseline: 1.5019x; 1.1687x over previous
#include <cuda_runtime.h>
#include <cstddef>

#define BB   4
#define CC   16
#define HH   256
#define WW   256
#define EPSF 1e-20f

// Two-stage split kernel, float4 width.
// Block = 256 threads = 16 pixel-quads x 16 channels.
// Stage 1: thread (p, c) computes spatial nom/den for one channel of one
//          pixel-quad (4 adjacent pixels, float4 loads), writes to smem.
// Stage 2: thread (p, o) does the 16-wide channel mix from smem and stores.
__global__ __launch_bounds__(256, 3)
void struct_nconv_q4_kernel(const float* __restrict__ d,
                            const float* __restrict__ cd,
                            const float* __restrict__ spr,
                            const float* __restrict__ swg,
                            const float* __restrict__ cwg,
                            float* __restrict__ out)
{
    __shared__ float  s_sw[144];        // spatial_weight[c*9+k]
    __shared__ float  s_cw[256];        // channel_weight[o*16+c]
    __shared__ float  s_sums[2];        // {sum(sw), sum(cw)}
    __shared__ float4 s_nom[16][16];    // [c][p]
    __shared__ float4 s_den[16][16];    // [c][p]

    const int tid = threadIdx.x;
    if (tid < 144) s_sw[tid] = swg[tid];
    s_cw[tid] = cwg[tid];
    __syncthreads();

    const int warp = tid >> 5, lane = tid & 31;
    if (warp == 0) {
        float v = 0.f;
        #pragma unroll
        for (int j = 0; j < 5; ++j) {
            int idx = lane + 32 * j;
            if (idx < 144) v += s_sw[idx];
        }
        #pragma unroll
        for (int off = 16; off; off >>= 1) v += __shfl_down_sync(0xffffffffu, v, off);
        if (lane == 0) s_sums[0] = v;
    } else if (warp == 1) {
        float v = 0.f;
        #pragma unroll
        for (int j = 0; j < 8; ++j) v += s_cw[lane + 32 * j];
        #pragma unroll
        for (int off = 16; off; off >>= 1) v += __shfl_down_sync(0xffffffffu, v, off);
        if (lane == 0) s_sums[1] = v;
    }

    // ---------------- Stage 1: spatial nom/den, one channel per thread ----
    const int p  = tid & 15;               // pixel-quad within block
    const int c  = tid >> 4;               // channel
    const int q  = blockIdx.x * 16 + p;    // global pixel-quad 0..65535
    const int w0 = (q & 63) << 2;
    const int h  = (q >> 6) & 255;
    const int b  = q >> 14;

    const bool wl = (w0 > 0);
    const bool wr = (w0 + 4 < WW);

    const size_t HW = (size_t)HH * WW;
    const float* dC  = d   + ((size_t)b * CC + c) * HW;
    const float* cdC = cd  + ((size_t)b * CC + c) * HW;
    const float* spC = spr + ((size_t)b * CC + c) * 9 * HW + (size_t)h * WW + w0;

    float swr[9];
    #pragma unroll
    for (int k = 0; k < 9; ++k) swr[k] = s_sw[c * 9 + k];

    float nom[4] = {0.f, 0.f, 0.f, 0.f};
    float den[4] = {0.f, 0.f, 0.f, 0.f};

    #pragma unroll
    for (int i = 0; i < 3; ++i) {
        const int hh = h + i - 1;
        const bool rok = (hh >= 0) && (hh < HH);
        const float* dR  = dC  + (size_t)hh * WW + w0;
        const float* cdR = cdC + (size_t)hh * WW + w0;

        const float4 z4 = make_float4(0.f, 0.f, 0.f, 0.f);
        float  dm  = (rok && wl) ? dR[-1]  : 0.f;
        float4 dc4 = rok ? *(const float4*)dR  : z4;
        float  dp  = (rok && wr) ? dR[4]   : 0.f;
        float  cm  = (rok && wl) ? cdR[-1] : 0.f;
        float4 cc4 = rok ? *(const float4*)cdR : z4;
        float  cp  = (rok && wr) ? cdR[4]  : 0.f;

        const float dw[6]  = { dm, dc4.x, dc4.y, dc4.z, dc4.w, dp };
        const float cdw[6] = { cm, cc4.x, cc4.y, cc4.z, cc4.w, cp };

        #pragma unroll
        for (int j = 0; j < 3; ++j) {
            const int k = i * 3 + j;
            const float4 sp  = *(const float4*)(spC + (size_t)k * HW);
            const float  swv = swr[k];
            const float spv[4] = { sp.x, sp.y, sp.z, sp.w };
            #pragma unroll
            for (int l = 0; l < 4; ++l) {
                const float t = cdw[j + l] * spv[l];
                den[l] = fmaf(t, swv, den[l]);
                nom[l] = fmaf(t * dw[j + l], swv, nom[l]);
            }
        }
    }

    s_nom[c][p] = make_float4(nom[0], nom[1], nom[2], nom[3]);
    s_den[c][p] = make_float4(den[0], den[1], den[2], den[3]);
    __syncthreads();

    // ---------------- Stage 2: channel mix, one output channel per thread --
    const int o = c;   // same (p, b, h, w0)

    float aN[4] = {0.f, 0.f, 0.f, 0.f};
    float aD[4] = {0.f, 0.f, 0.f, 0.f};
    #pragma unroll
    for (int cc = 0; cc < 16; ++cc) {
        const float4 nd = s_nom[cc][p];
        const float4 dd = s_den[cc][p];
        const float  cwv = s_cw[o * 16 + cc];
        aN[0] = fmaf(nd.x, cwv, aN[0]);
        aN[1] = fmaf(nd.y, cwv, aN[1]);
        aN[2] = fmaf(nd.z, cwv, aN[2]);
        aN[3] = fmaf(nd.w, cwv, aN[3]);
        aD[0] = fmaf(dd.x, cwv, aD[0]);
        aD[1] = fmaf(dd.y, cwv, aD[1]);
        aD[2] = fmaf(dd.z, cwv, aD[2]);
        aD[3] = fmaf(dd.w, cwv, aD[3]);
    }

    // d_out = N/(D+EPS)  (EPS-cancellation, error O(1e-19))
    // cd_out = D / ((sum sw + eps)(sum cw + eps))   (devalue_conf = 1)
    const float inv_cw = 1.0f / ((s_sums[0] + EPSF) * (s_sums[1] + EPSF));

    float4 dov, cdo;
    dov.x = aN[0] / (aD[0] + EPSF);
    dov.y = aN[1] / (aD[1] + EPSF);
    dov.z = aN[2] / (aD[2] + EPSF);
    dov.w = aN[3] / (aD[3] + EPSF);
    cdo.x = aD[0] * inv_cw;
    cdo.y = aD[1] * inv_cw;
    cdo.z = aD[2] * inv_cw;
    cdo.w = aD[3] * inv_cw;

    const size_t Ntot = (size_t)BB * CC * HW;
    const size_t idx  = ((size_t)b * CC + o) * HW + (size_t)h * WW + w0;
    *(float4*)(out + idx)        = dov;
    *(float4*)(out + Ntot + idx) = cdo;
}

extern "C" void kernel_launch(void* const* d_in, const int* in_sizes, int n_in,
                              void* d_out, int out_size)
{
    const float* d   = (const float*)d_in[0];
    const float* cd  = (const float*)d_in[1];
    // d_in[2] = s, d_in[3] = cs : unused by the reference computation
    const float* spr = (const float*)d_in[4];
    const float* sw  = (const float*)d_in[5];
    const float* cw  = (const float*)d_in[6];
    float* out = (float*)d_out;

    // 65536 pixel-quads / 16 per block = 4096 blocks
    struct_nconv_q4_kernel<<<4096, 256>>>(d, cd, spr, sw, cw, out);
}